// round 5
// baseline (speedup 1.0000x reference)
#include <cuda_runtime.h>
#include <math.h>
#include <stdint.h>

#define Bb 8
#define Tt 8192
#define Ss 8192
#define Ff 64
#define Dd 64
#define EPSf 1e-9f
#define KVPAD 72
#define ASPLITS 32
#define AROWS (Ss/ASPLITS)   /* 256 rows per block in kv kernel */

// kv scratch [b][256][72]; cols 65..71 stay zero
__device__ __align__(16) float g_kv[Bb * 256 * KVPAD];

// ---------------------------------------------------------------------------
// helpers
// ---------------------------------------------------------------------------
__device__ __forceinline__ float ftf32(float x) {
    unsigned u;
    asm("cvt.rna.tf32.f32 %0, %1;" : "=r"(u) : "f"(x));
    return __uint_as_float(u);
}

__device__ __forceinline__ void mma8(float4& d,
                                     float a0, float a1, float a2, float a3,
                                     float b0, float b1) {
    asm("mma.sync.aligned.m16n8k8.row.col.f32.tf32.tf32.f32 "
        "{%0,%1,%2,%3},{%4,%5,%6,%7},{%8,%9},{%0,%1,%2,%3};"
        : "+f"(d.x), "+f"(d.y), "+f"(d.z), "+f"(d.w)
        : "r"(__float_as_uint(a0)), "r"(__float_as_uint(a1)),
          "r"(__float_as_uint(a2)), "r"(__float_as_uint(a3)),
          "r"(__float_as_uint(b0)), "r"(__float_as_uint(b1)));
}

__global__ void zero_kv_kernel() {
    int i = blockIdx.x * blockDim.x + threadIdx.x;
    if (i < Bb * 256 * KVPAD) g_kv[i] = 0.0f;
}

// ---------------------------------------------------------------------------
// smem layouts (float offsets)
// ---------------------------------------------------------------------------
// kernel A
#define A_KS   0        /* [64][68]  */
#define A_VS   4352     /* [64][72]  */
#define A_PHT  8960     /* [256][68] */
#define A_OHI  26368    /* [128][68] */
#define A_OLO  35072    /* [128][68] */
#define A_SSH  43776    /* [64]      */
#define A_PRT  43840    /* [256]     */
#define A_TOT  44096
// kernel B
#define B_PHIQ 0        /* [128][260], aliases Qs/Ohi/Olo during phase 1 */
#define B_QS   0        /* [128][68]  */
#define B_OHI  8704     /* [128][68]  */
#define B_OLO  17408    /* [128][68]  */
#define B_KVS  33280    /* [256][72]  */
#define B_SSH  51712    /* [128]      */
#define B_PRT  51840    /* [256]      */
#define B_TOT  52096

extern __shared__ float sm[];

// ---------------------------------------------------------------------------
// Kernel A: fused  K -> phi_k -> kv partial (split-K over S, atomics)
// block: 256 thr / 8 warps, 2 blocks/SM.  Per 64-row chunk:
//   XW[64x128] = K_chunk . Omega^T   (split tf32: 3 mma passes)
//   PhT[256][64] = exp(+-XW - ss) + eps   (tf32-rounded, stored transposed)
//   acc[256x64] += PhT . V_chunk ; normalizer via direct register sum
// ---------------------------------------------------------------------------
__global__ __launch_bounds__(256, 2)
void kv_kernel(const float* __restrict__ key,
               const float* __restrict__ value,
               const float* __restrict__ omega) {
    const int b   = blockIdx.y;
    const int tid = threadIdx.x;
    const int w   = tid >> 5;
    const int ln  = tid & 31;
    const int gid = ln >> 2;
    const int tq  = ln & 3;

    float* Ks  = sm + A_KS;
    float* Vs  = sm + A_VS;
    float* PhT = sm + A_PHT;
    float* Ohi = sm + A_OHI;
    float* Olo = sm + A_OLO;
    float* ssh = sm + A_SSH;
    float* prt = sm + A_PRT;

    // omega -> hi/lo tf32 split in smem
    for (int i = tid; i < 128 * 64; i += 256) {
        int m = i >> 6, f = i & 63;
        float x  = omega[i];
        float hi = ftf32(x);
        Ohi[m * 68 + f] = hi;
        Olo[m * 68 + f] = ftf32(x - hi);
    }

    float4 acc[2][8];
    #pragma unroll
    for (int mt = 0; mt < 2; mt++)
        #pragma unroll
        for (int nt = 0; nt < 8; nt++)
            acc[mt][nt] = make_float4(0.f, 0.f, 0.f, 0.f);
    float nrm[2][2] = {{0.f, 0.f}, {0.f, 0.f}};   // [mt][row half]

    const int row0base = blockIdx.x * AROWS;

    for (int c = 0; c < AROWS / 64; c++) {
        __syncthreads();   // previous-iter PhT reads done before overwrite
        const int row0 = row0base + c * 64;

        // ---- load K chunk (+ssq partials) and V chunk (tf32-rounded) ----
        {
            int r = tid >> 2, qd = tid & 3;
            const float4* kg = (const float4*)(key + ((size_t)(b * Ss + row0 + r)) * Ff);
            float ps = 0.f;
            #pragma unroll
            for (int j = 0; j < 4; j++) {
                float4 x = kg[qd * 4 + j];
                ps += x.x * x.x + x.y * x.y + x.z * x.z + x.w * x.w;
                ((float4*)(Ks + r * 68))[qd * 4 + j] = x;
            }
            prt[tid] = ps;
            const float4* vg = (const float4*)(value + ((size_t)(b * Ss + row0 + r)) * Dd);
            #pragma unroll
            for (int j = 0; j < 4; j++) {
                float4 x = vg[qd * 4 + j];
                float4 y;
                y.x = ftf32(x.x); y.y = ftf32(x.y); y.z = ftf32(x.z); y.w = ftf32(x.w);
                ((float4*)(Vs + r * 72))[qd * 4 + j] = y;
            }
        }
        __syncthreads();
        if (tid < 64)
            ssh[tid] = 0.5f * (prt[tid * 4] + prt[tid * 4 + 1] +
                               prt[tid * 4 + 2] + prt[tid * 4 + 3]);
        __syncthreads();

        // ---- XW = K . Omega^T  (M=64 s-rows, warp w owns features [16w,16w+16)) ----
        float4 xw[4][2];
        #pragma unroll
        for (int mt = 0; mt < 4; mt++)
            #pragma unroll
            for (int nt = 0; nt < 2; nt++)
                xw[mt][nt] = make_float4(0.f, 0.f, 0.f, 0.f);

        for (int ks = 0; ks < 8; ks++) {
            int f0 = ks * 8 + tq;
            float bh[2][2], bl[2][2];
            #pragma unroll
            for (int nt = 0; nt < 2; nt++) {
                int m = w * 16 + nt * 8 + gid;
                bh[nt][0] = Ohi[m * 68 + f0];     bh[nt][1] = Ohi[m * 68 + f0 + 4];
                bl[nt][0] = Olo[m * 68 + f0];     bl[nt][1] = Olo[m * 68 + f0 + 4];
            }
            #pragma unroll
            for (int mt = 0; mt < 4; mt++) {
                int s = mt * 16 + gid;
                float a0 = Ks[s * 68 + f0],       a1 = Ks[(s + 8) * 68 + f0];
                float a2 = Ks[s * 68 + f0 + 4],   a3 = Ks[(s + 8) * 68 + f0 + 4];
                float h0 = ftf32(a0), h1 = ftf32(a1), h2 = ftf32(a2), h3 = ftf32(a3);
                float l0 = ftf32(a0 - h0), l1 = ftf32(a1 - h1);
                float l2 = ftf32(a2 - h2), l3 = ftf32(a3 - h3);
                #pragma unroll
                for (int nt = 0; nt < 2; nt++) {
                    mma8(xw[mt][nt], h0, h1, h2, h3, bh[nt][0], bh[nt][1]);
                    mma8(xw[mt][nt], l0, l1, l2, l3, bh[nt][0], bh[nt][1]);
                    mma8(xw[mt][nt], h0, h1, h2, h3, bl[nt][0], bl[nt][1]);
                }
            }
        }

        // ---- phi epilogue: PhT[m][s] = tf32(exp(+-xw - ss) + eps) ----
        #pragma unroll
        for (int mt = 0; mt < 4; mt++) {
            int s0 = mt * 16 + gid;
            float ssa = ssh[s0], ssb = ssh[s0 + 8];
            #pragma unroll
            for (int nt = 0; nt < 2; nt++) {
                int m0 = w * 16 + nt * 8 + 2 * tq;
                float4 v = xw[mt][nt];
                PhT[m0 * 68 + s0]             = ftf32(__expf( v.x - ssa) + EPSf);
                PhT[(m0 + 1) * 68 + s0]       = ftf32(__expf( v.y - ssa) + EPSf);
                PhT[m0 * 68 + s0 + 8]         = ftf32(__expf( v.z - ssb) + EPSf);
                PhT[(m0 + 1) * 68 + s0 + 8]   = ftf32(__expf( v.w - ssb) + EPSf);
                PhT[(m0 + 128) * 68 + s0]     = ftf32(__expf(-v.x - ssa) + EPSf);
                PhT[(m0 + 129) * 68 + s0]     = ftf32(__expf(-v.y - ssa) + EPSf);
                PhT[(m0 + 128) * 68 + s0 + 8] = ftf32(__expf(-v.z - ssb) + EPSf);
                PhT[(m0 + 129) * 68 + s0 + 8] = ftf32(__expf(-v.w - ssb) + EPSf);
            }
        }
        __syncthreads();

        // ---- acc += PhT . V   (warp w owns kv rows [32w, 32w+32)) ----
        #pragma unroll 2
        for (int ks = 0; ks < 8; ks++) {
            float a[2][4];
            #pragma unroll
            for (int mt = 0; mt < 2; mt++) {
                int mr = 32 * w + mt * 16 + gid;
                int sc = ks * 8 + tq;
                a[mt][0] = PhT[mr * 68 + sc];
                a[mt][1] = PhT[(mr + 8) * 68 + sc];
                a[mt][2] = PhT[mr * 68 + sc + 4];
                a[mt][3] = PhT[(mr + 8) * 68 + sc + 4];
                // normalizer: every phi value of this thread's rows appears
                // exactly once across (c, ks, j) -> direct fp32 sum
                nrm[mt][0] += a[mt][0] + a[mt][2];
                nrm[mt][1] += a[mt][1] + a[mt][3];
            }
            #pragma unroll
            for (int nt = 0; nt < 8; nt++) {
                float b0 = Vs[(ks * 8 + tq) * 72 + nt * 8 + gid];
                float b1 = Vs[(ks * 8 + tq + 4) * 72 + nt * 8 + gid];
                #pragma unroll
                for (int mt = 0; mt < 2; mt++)
                    mma8(acc[mt][nt], a[mt][0], a[mt][1], a[mt][2], a[mt][3], b0, b1);
            }
        }
    }

    // ---- atomic reduce into g_kv ----
    float* gp = g_kv + (size_t)b * 256 * KVPAD;
    #pragma unroll
    for (int mt = 0; mt < 2; mt++) {
        int m0 = 32 * w + mt * 16 + gid;
        #pragma unroll
        for (int nt = 0; nt < 8; nt++) {
            int d0 = nt * 8 + 2 * tq;
            atomicAdd(gp + m0 * KVPAD + d0,           acc[mt][nt].x);
            atomicAdd(gp + m0 * KVPAD + d0 + 1,       acc[mt][nt].y);
            atomicAdd(gp + (m0 + 8) * KVPAD + d0,     acc[mt][nt].z);
            atomicAdd(gp + (m0 + 8) * KVPAD + d0 + 1, acc[mt][nt].w);
        }
        // normalizer column: reduce across the 4 tq lanes of the quad
        float n0 = nrm[mt][0], n1 = nrm[mt][1];
        n0 += __shfl_xor_sync(0xffffffffu, n0, 1);
        n0 += __shfl_xor_sync(0xffffffffu, n0, 2);
        n1 += __shfl_xor_sync(0xffffffffu, n1, 1);
        n1 += __shfl_xor_sync(0xffffffffu, n1, 2);
        if (tq == 0) {
            atomicAdd(gp + m0 * KVPAD + 64,       n0);
            atomicAdd(gp + (m0 + 8) * KVPAD + 64, n1);
        }
    }
}

// ---------------------------------------------------------------------------
// Kernel B: fused  Q -> phi_q -> out = (phi_q . kv) / normalizer
// block: 256 thr / 8 warps, 2 blocks/SM, 128 t-rows per block.
// ---------------------------------------------------------------------------
__global__ __launch_bounds__(256, 2)
void out_kernel(const float* __restrict__ query,
                const float* __restrict__ omega,
                float* __restrict__ outp) {
    const int b   = blockIdx.y;
    const int t0  = blockIdx.x * 128;
    const int tid = threadIdx.x;
    const int w   = tid >> 5;
    const int ln  = tid & 31;
    const int gid = ln >> 2;
    const int tq  = ln & 3;

    float* PhiQ = sm + B_PHIQ;
    float* Qs   = sm + B_QS;
    float* Ohi  = sm + B_OHI;
    float* Olo  = sm + B_OLO;
    float* kvs  = sm + B_KVS;
    float* ssh  = sm + B_SSH;
    float* prt  = sm + B_PRT;

    // ---- phase-1 loads: Q tile, omega hi/lo, kv (tf32-rounded) ----
    {
        int r = tid >> 1, h = tid & 1;
        const float4* qg = (const float4*)(query + ((size_t)(b * Tt + t0 + r)) * Ff);
        float ps = 0.f;
        #pragma unroll
        for (int j = 0; j < 8; j++) {
            float4 x = qg[h * 8 + j];
            ps += x.x * x.x + x.y * x.y + x.z * x.z + x.w * x.w;
            ((float4*)(Qs + r * 68))[h * 8 + j] = x;
        }
        prt[tid] = ps;
    }
    for (int i = tid; i < 128 * 64; i += 256) {
        int m = i >> 6, f = i & 63;
        float x  = omega[i];
        float hi = ftf32(x);
        Ohi[m * 68 + f] = hi;
        Olo[m * 68 + f] = ftf32(x - hi);
    }
    {
        const float4* gk = (const float4*)(g_kv + (size_t)b * 256 * KVPAD);
        for (int i = tid; i < 256 * KVPAD / 4; i += 256) {
            float4 x = gk[i];
            float4 y;
            y.x = ftf32(x.x); y.y = ftf32(x.y); y.z = ftf32(x.z); y.w = ftf32(x.w);
            ((float4*)kvs)[i] = y;
        }
    }
    __syncthreads();
    if (tid < 128) ssh[tid] = 0.5f * (prt[2 * tid] + prt[2 * tid + 1]);
    __syncthreads();

    // ---- XW = Q . Omega^T  (M=128 t-rows, warp w owns features [16w,16w+16)) ----
    float4 xw[8][2];
    #pragma unroll
    for (int mt = 0; mt < 8; mt++)
        #pragma unroll
        for (int nt = 0; nt < 2; nt++)
            xw[mt][nt] = make_float4(0.f, 0.f, 0.f, 0.f);

    for (int ks = 0; ks < 8; ks++) {
        int f0 = ks * 8 + tq;
        float bh[2][2], bl[2][2];
        #pragma unroll
        for (int nt = 0; nt < 2; nt++) {
            int m = w * 16 + nt * 8 + gid;
            bh[nt][0] = Ohi[m * 68 + f0];   bh[nt][1] = Ohi[m * 68 + f0 + 4];
            bl[nt][0] = Olo[m * 68 + f0];   bl[nt][1] = Olo[m * 68 + f0 + 4];
        }
        #pragma unroll
        for (int mt = 0; mt < 8; mt++) {
            int t = mt * 16 + gid;
            float a0 = Qs[t * 68 + f0],       a1 = Qs[(t + 8) * 68 + f0];
            float a2 = Qs[t * 68 + f0 + 4],   a3 = Qs[(t + 8) * 68 + f0 + 4];
            float h0 = ftf32(a0), h1 = ftf32(a1), h2 = ftf32(a2), h3 = ftf32(a3);
            float l0 = ftf32(a0 - h0), l1 = ftf32(a1 - h1);
            float l2 = ftf32(a2 - h2), l3 = ftf32(a3 - h3);
            #pragma unroll
            for (int nt = 0; nt < 2; nt++) {
                mma8(xw[mt][nt], h0, h1, h2, h3, bh[nt][0], bh[nt][1]);
                mma8(xw[mt][nt], l0, l1, l2, l3, bh[nt][0], bh[nt][1]);
                mma8(xw[mt][nt], h0, h1, h2, h3, bl[nt][0], bl[nt][1]);
            }
        }
    }
    __syncthreads();   // all Qs/omega reads done; PhiQ may overwrite them now

    // ---- phi epilogue: PhiQ[t][m] = tf32(exp(+-xw - ss) + eps) ----
    #pragma unroll
    for (int mt = 0; mt < 8; mt++) {
        int t = mt * 16 + gid;
        float ssa = ssh[t], ssb = ssh[t + 8];
        #pragma unroll
        for (int nt = 0; nt < 2; nt++) {
            int m0 = w * 16 + nt * 8 + 2 * tq;
            float4 v = xw[mt][nt];
            PhiQ[t * 260 + m0]             = ftf32(__expf( v.x - ssa) + EPSf);
            PhiQ[t * 260 + m0 + 1]         = ftf32(__expf( v.y - ssa) + EPSf);
            PhiQ[(t + 8) * 260 + m0]       = ftf32(__expf( v.z - ssb) + EPSf);
            PhiQ[(t + 8) * 260 + m0 + 1]   = ftf32(__expf( v.w - ssb) + EPSf);
            PhiQ[t * 260 + m0 + 128]       = ftf32(__expf(-v.x - ssa) + EPSf);
            PhiQ[t * 260 + m0 + 129]       = ftf32(__expf(-v.y - ssa) + EPSf);
            PhiQ[(t + 8) * 260 + m0 + 128] = ftf32(__expf(-v.z - ssb) + EPSf);
            PhiQ[(t + 8) * 260 + m0 + 129] = ftf32(__expf(-v.w - ssb) + EPSf);
        }
    }
    __syncthreads();

    // ---- out = PhiQ . kv  (warp w owns t-rows [16w,16w+16), K=256) ----
    float4 oacc[9];
    #pragma unroll
    for (int nt = 0; nt < 9; nt++) oacc[nt] = make_float4(0.f, 0.f, 0.f, 0.f);

    #pragma unroll 4
    for (int ks = 0; ks < 32; ks++) {
        int tr = 16 * w + gid;
        int mc = ks * 8 + tq;
        float a0 = PhiQ[tr * 260 + mc],       a1 = PhiQ[(tr + 8) * 260 + mc];
        float a2 = PhiQ[tr * 260 + mc + 4],   a3 = PhiQ[(tr + 8) * 260 + mc + 4];
        #pragma unroll
        for (int nt = 0; nt < 9; nt++) {
            float b0 = kvs[(ks * 8 + tq) * KVPAD + nt * 8 + gid];
            float b1 = kvs[(ks * 8 + tq + 4) * KVPAD + nt * 8 + gid];
            mma8(oacc[nt], a0, a1, a2, a3, b0, b1);
        }
    }

    // ---- normalize (normalizer col 64 lives in n-tile 8, lanes tq==0) ----
    float n0 = __shfl_sync(0xffffffffu, oacc[8].x, ln & ~3);
    float n1 = __shfl_sync(0xffffffffu, oacc[8].z, ln & ~3);
    float inv0 = 1.0f / n0;
    float inv1 = 1.0f / n1;

    size_t orow = ((size_t)b * Tt + t0 + 16 * w + gid) * 64;
    #pragma unroll
    for (int nt = 0; nt < 8; nt++) {
        int col = nt * 8 + 2 * tq;
        float2 r0 = make_float2(oacc[nt].x * inv0, oacc[nt].y * inv0);
        float2 r1 = make_float2(oacc[nt].z * inv1, oacc[nt].w * inv1);
        *(float2*)(outp + orow + col)          = r0;
        *(float2*)(outp + orow + 8 * 64 + col) = r1;
    }
}

// ---------------------------------------------------------------------------
// launch
// ---------------------------------------------------------------------------
extern "C" void kernel_launch(void* const* d_in, const int* in_sizes, int n_in,
                              void* d_out, int out_size) {
    const float* query = (const float*)d_in[0];
    const float* value = (const float*)d_in[1];
    const float* key   = (const float*)d_in[2];
    const float* omega = (const float*)d_in[3];
    float* out = (float*)d_out;

    cudaFuncSetAttribute(kv_kernel,  cudaFuncAttributeMaxDynamicSharedMemorySize,
                         A_TOT * (int)sizeof(float));
    cudaFuncSetAttribute(out_kernel, cudaFuncAttributeMaxDynamicSharedMemorySize,
                         B_TOT * (int)sizeof(float));

    zero_kv_kernel<<<(Bb * 256 * KVPAD + 255) / 256, 256>>>();
    kv_kernel<<<dim3(ASPLITS, Bb), 256, A_TOT * sizeof(float)>>>(key, value, omega);
    out_kernel<<<dim3(Tt / 128, Bb), 256, B_TOT * sizeof(float)>>>(query, omega, out);
}